// round 2
// baseline (speedup 1.0000x reference)
#include <cuda_runtime.h>
#include <math.h>

#define NROWS 16384
#define DDIM 64
#define HDIM 1024
#define NFREQ 4096

// ---------------- scratch (static device allocations; allowed) ----------------
__device__ float g_h1[(size_t)NROWS * HDIM];
__device__ float g_h2[(size_t)NROWS * HDIM];
__device__ float g_x[(size_t)NROWS * DDIM];
__device__ float g_inner[(size_t)NROWS * NFREQ];   // 256 MB
__device__ float g_V[(size_t)NROWS * DDIM];
__device__ float g_sCx[NFREQ];
__device__ float g_sSx[NFREQ];
__device__ float g_sCy[NFREQ];
__device__ float g_sSy[NFREQ];
__device__ float g_errC[NFREQ];
__device__ float g_errS[NFREQ];
__device__ float g_rowsq[NROWS];
__device__ float g_vtot;

__device__ __forceinline__ float selu_f(float v) {
    const float alpha = 1.6732632423543772f;
    const float scale = 1.0507009873554805f;
    return v > 0.0f ? scale * v : scale * alpha * expm1f(v);
}

__global__ void zero_kernel() {
    int i = blockIdx.x * blockDim.x + threadIdx.x;
    if (i < NFREQ) {
        g_sCx[i] = 0.f; g_sSx[i] = 0.f; g_sCy[i] = 0.f; g_sSy[i] = 0.f;
    }
    if (i == 0) g_vtot = 0.f;
}

// ---------------- fp32 tiled GEMM + bias (+SELU) ----------------
// C[M,N] = act(A[M,K] @ W[K,N] + b[N])
template<int BM, int BN, int BK, int TM, int TN, bool ACT>
__global__ void __launch_bounds__((BM / TM) * (BN / TN))
gemm_bias_act(const float* __restrict__ A, const float* __restrict__ W,
              const float* __restrict__ bias, float* __restrict__ C,
              int M, int N, int K)
{
    constexpr int THREADS = (BM / TM) * (BN / TN);
    __shared__ float As[BK][BM + 4];
    __shared__ float Ws[BK][BN];
    const int tx = threadIdx.x;
    const int tcol = tx % (BN / TN);
    const int trow = tx / (BN / TN);
    const int rowBase = blockIdx.y * BM;
    const int colBase = blockIdx.x * BN;

    float acc[TM][TN];
#pragma unroll
    for (int i = 0; i < TM; i++)
#pragma unroll
        for (int j = 0; j < TN; j++) acc[i][j] = 0.f;

    for (int k0 = 0; k0 < K; k0 += BK) {
        // A tile (BM x BK) -> As[k][m]  (float4 global loads)
        for (int i = tx; i < BM * (BK / 4); i += THREADS) {
            int m = i / (BK / 4);
            int kq = (i % (BK / 4)) * 4;
            const float4 v = *reinterpret_cast<const float4*>(
                &A[(size_t)(rowBase + m) * K + k0 + kq]);
            As[kq + 0][m] = v.x; As[kq + 1][m] = v.y;
            As[kq + 2][m] = v.z; As[kq + 3][m] = v.w;
        }
        // W tile (BK x BN)
        for (int i = tx; i < BK * (BN / 4); i += THREADS) {
            int kk = i / (BN / 4);
            int nq = (i % (BN / 4)) * 4;
            *reinterpret_cast<float4*>(&Ws[kk][nq]) =
                *reinterpret_cast<const float4*>(
                    &W[(size_t)(k0 + kk) * N + colBase + nq]);
        }
        __syncthreads();
#pragma unroll
        for (int kk = 0; kk < BK; kk++) {
            float a[TM], w[TN];
#pragma unroll
            for (int i = 0; i < TM; i++) a[i] = As[kk][trow * TM + i];
#pragma unroll
            for (int j = 0; j < TN; j++) w[j] = Ws[kk][tcol * TN + j];
#pragma unroll
            for (int i = 0; i < TM; i++)
#pragma unroll
                for (int j = 0; j < TN; j++)
                    acc[i][j] = fmaf(a[i], w[j], acc[i][j]);
        }
        __syncthreads();
    }
#pragma unroll
    for (int i = 0; i < TM; i++) {
        const int m = rowBase + trow * TM + i;
#pragma unroll
        for (int j = 0; j < TN; j++) {
            const int n = colBase + tcol * TN + j;
            float v = acc[i][j] + bias[n];
            if (ACT) v = selu_f(v);
            C[(size_t)m * N + n] = v;
        }
    }
}

// ---------------- pass 1: inner = X @ (2*Fr)^T, column means of cos/sin ------
// Block: 128 rows x 128 freqs, 256 threads, 8x8 per thread. K = 64 (full).
template<bool STORE>
__global__ void __launch_bounds__(256)
inner_pass(const float* __restrict__ X, const float* __restrict__ Fr,
           float* __restrict__ sumC, float* __restrict__ sumS)
{
    extern __shared__ float sm[];
    float* Xs = sm;               // [64][129] : Xs[k*129 + r]
    float* Fs = sm + 64 * 129;    // [64][129] : Fs[k*129 + f]
    __shared__ float redC[128];
    __shared__ float redS[128];

    const int tx = threadIdx.x;
    const int rowBase = blockIdx.y * 128;
    const int fBase = blockIdx.x * 128;

    for (int q = tx; q < 128 * 16; q += 256) {
        int r = q >> 4;
        int d4 = (q & 15) << 2;
        float4 v = *reinterpret_cast<const float4*>(
            &X[(size_t)(rowBase + r) * DDIM + d4]);
        Xs[(d4 + 0) * 129 + r] = v.x;
        Xs[(d4 + 1) * 129 + r] = v.y;
        Xs[(d4 + 2) * 129 + r] = v.z;
        Xs[(d4 + 3) * 129 + r] = v.w;
    }
    for (int q = tx; q < 128 * 16; q += 256) {
        int f = q >> 4;
        int d4 = (q & 15) << 2;
        float4 v = *reinterpret_cast<const float4*>(
            &Fr[(size_t)(fBase + f) * DDIM + d4]);
        Fs[(d4 + 0) * 129 + f] = 2.0f * v.x;
        Fs[(d4 + 1) * 129 + f] = 2.0f * v.y;
        Fs[(d4 + 2) * 129 + f] = 2.0f * v.z;
        Fs[(d4 + 3) * 129 + f] = 2.0f * v.w;
    }
    __syncthreads();

    const int trow = tx >> 4;   // 0..15 (row group of 8)
    const int tcol = tx & 15;   // 0..15 (freq group of 8)

    float acc[8][8];
#pragma unroll
    for (int i = 0; i < 8; i++)
#pragma unroll
        for (int j = 0; j < 8; j++) acc[i][j] = 0.f;

#pragma unroll 8
    for (int k = 0; k < 64; k++) {
        float a[8], w[8];
#pragma unroll
        for (int i = 0; i < 8; i++) a[i] = Xs[k * 129 + trow * 8 + i];
#pragma unroll
        for (int j = 0; j < 8; j++) w[j] = Fs[k * 129 + tcol * 8 + j];
#pragma unroll
        for (int i = 0; i < 8; i++)
#pragma unroll
            for (int j = 0; j < 8; j++)
                acc[i][j] = fmaf(a[i], w[j], acc[i][j]);
    }

    float cpart[8], spart[8];
#pragma unroll
    for (int j = 0; j < 8; j++) { cpart[j] = 0.f; spart[j] = 0.f; }

#pragma unroll
    for (int i = 0; i < 8; i++) {
        if (STORE) {
            size_t base = (size_t)(rowBase + trow * 8 + i) * NFREQ + fBase + tcol * 8;
            float4 v0 = make_float4(acc[i][0], acc[i][1], acc[i][2], acc[i][3]);
            float4 v1 = make_float4(acc[i][4], acc[i][5], acc[i][6], acc[i][7]);
            *reinterpret_cast<float4*>(&g_inner[base]) = v0;
            *reinterpret_cast<float4*>(&g_inner[base + 4]) = v1;
        }
#pragma unroll
        for (int j = 0; j < 8; j++) {
            float s, c;
            sincosf(acc[i][j], &s, &c);
            cpart[j] += c;
            spart[j] += s;
        }
    }

    if (tx < 128) { redC[tx] = 0.f; redS[tx] = 0.f; }
    __syncthreads();
#pragma unroll
    for (int j = 0; j < 8; j++) {
        atomicAdd(&redC[tcol * 8 + j], cpart[j]);
        atomicAdd(&redS[tcol * 8 + j], spart[j]);
    }
    __syncthreads();
    if (tx < 128) {
        atomicAdd(&sumC[fBase + tx], redC[tx]);
        atomicAdd(&sumS[fBase + tx], redS[tx]);
    }
}

__global__ void err_kernel() {
    int f = blockIdx.x * blockDim.x + threadIdx.x;
    if (f < NFREQ) {
        const float inv = 1.0f / (float)NROWS;   // N == M == 16384
        g_errC[f] = (g_sCx[f] - g_sCy[f]) * inv;
        g_errS[f] = (g_sSx[f] - g_sSy[f]) * inv;
    }
}

// ---------------- pass 2: V = (-2/(N*NF)) * coeff @ F ------------------------
// Block: 64 rows, loop over freq in chunks of 128. 256 threads.
// coeff computed in smem from stored inner; then smem GEMM 64x64x128 per chunk.
__global__ void __launch_bounds__(256)
pass2_kernel(const float* __restrict__ Fr)
{
    extern __shared__ float sm[];
    float* coeffS = sm;                 // [64][129]
    float* Fs = sm + 64 * 129;          // [128][68]
    __shared__ float eC[128];
    __shared__ float eS[128];

    const int tx = threadIdx.x;
    const int rowBase = blockIdx.x * 64;
    const int trow = tx >> 4;   // 0..15 -> rows trow*4..+3
    const int tcol = tx & 15;   // 0..15 -> dims tcol*4..+3

    float acc[4][4];
#pragma unroll
    for (int i = 0; i < 4; i++)
#pragma unroll
        for (int j = 0; j < 4; j++) acc[i][j] = 0.f;

    for (int fc = 0; fc < NFREQ; fc += 128) {
        for (int q = tx; q < 128 * 16; q += 256) {
            int f = q >> 4;
            int d4 = (q & 15) << 2;
            float4 v = *reinterpret_cast<const float4*>(
                &Fr[(size_t)(fc + f) * DDIM + d4]);
            Fs[f * 68 + d4 + 0] = 2.0f * v.x;
            Fs[f * 68 + d4 + 1] = 2.0f * v.y;
            Fs[f * 68 + d4 + 2] = 2.0f * v.z;
            Fs[f * 68 + d4 + 3] = 2.0f * v.w;
        }
        if (tx < 128) { eC[tx] = g_errC[fc + tx]; eS[tx] = g_errS[fc + tx]; }
        __syncthreads();

        // coeff tile 64x128
        for (int e = tx; e < 64 * 128; e += 256) {
            int r = e >> 7;
            int fl = e & 127;
            float v = g_inner[(size_t)(rowBase + r) * NFREQ + fc + fl];
            float s, c;
            sincosf(v, &s, &c);
            coeffS[r * 129 + fl] = -eC[fl] * s + eS[fl] * c;
        }
        __syncthreads();

#pragma unroll 4
        for (int f = 0; f < 128; f++) {
            float a[4];
#pragma unroll
            for (int i = 0; i < 4; i++) a[i] = coeffS[(trow * 4 + i) * 129 + f];
            float4 wv = *reinterpret_cast<const float4*>(&Fs[f * 68 + tcol * 4]);
            float w[4] = { wv.x, wv.y, wv.z, wv.w };
#pragma unroll
            for (int i = 0; i < 4; i++)
#pragma unroll
                for (int j = 0; j < 4; j++)
                    acc[i][j] = fmaf(a[i], w[j], acc[i][j]);
        }
        __syncthreads();
    }

    const float fac = -2.0f / ((float)NROWS * (float)NFREQ);
#pragma unroll
    for (int i = 0; i < 4; i++) {
        const int m = rowBase + trow * 4 + i;
        float4 v = make_float4(acc[i][0] * fac, acc[i][1] * fac,
                               acc[i][2] * fac, acc[i][3] * fac);
        *reinterpret_cast<float4*>(&g_V[(size_t)m * DDIM + tcol * 4]) = v;
    }
}

// ---------------- row sum of squares + global total --------------------------
__global__ void __launch_bounds__(256)
rowsq_kernel()
{
    const int row = blockIdx.x * 8 + (threadIdx.x >> 5);
    const int lane = threadIdx.x & 31;
    float v0 = g_V[(size_t)row * DDIM + lane];
    float v1 = g_V[(size_t)row * DDIM + lane + 32];
    float s = v0 * v0 + v1 * v1;
#pragma unroll
    for (int o = 16; o > 0; o >>= 1) s += __shfl_down_sync(0xFFFFFFFFu, s, o);
    if (lane == 0) {
        g_rowsq[row] = s;
        atomicAdd(&g_vtot, s);
    }
}

__global__ void final_kernel(float* __restrict__ out)
{
    int i = blockIdx.x * blockDim.x + threadIdx.x;
    if (i < NROWS) {
        float mean = g_vtot * (1.0f / ((float)NROWS * (float)DDIM));
        out[i] = g_rowsq[i] / (mean + 1e-8f);
    }
}

// ---------------- launch -----------------------------------------------------
extern "C" void kernel_launch(void* const* d_in, const int* in_sizes, int n_in,
                              void* d_out, int out_size)
{
    const float* data = (const float*)d_in[0];
    const float* z    = (const float*)d_in[1];
    const float* Fr   = (const float*)d_in[2];
    const float* W1   = (const float*)d_in[3];
    const float* b1   = (const float*)d_in[4];
    const float* W2   = (const float*)d_in[5];
    const float* b2   = (const float*)d_in[6];
    const float* W3   = (const float*)d_in[7];
    const float* b3   = (const float*)d_in[8];
    const float* W4   = (const float*)d_in[9];
    const float* b4   = (const float*)d_in[10];
    const float* W5   = (const float*)d_in[11];
    const float* b5   = (const float*)d_in[12];
    float* out = (float*)d_out;

    float *h1, *h2, *x, *sCx, *sSx, *sCy, *sSy;
    cudaGetSymbolAddress((void**)&h1, g_h1);
    cudaGetSymbolAddress((void**)&h2, g_h2);
    cudaGetSymbolAddress((void**)&x, g_x);
    cudaGetSymbolAddress((void**)&sCx, g_sCx);
    cudaGetSymbolAddress((void**)&sSx, g_sSx);
    cudaGetSymbolAddress((void**)&sCy, g_sCy);
    cudaGetSymbolAddress((void**)&sSy, g_sSy);

    zero_kernel<<<(NFREQ + 255) / 256, 256>>>();

    // MLP
    {
        dim3 grid(HDIM / 128, NROWS / 128);
        gemm_bias_act<128, 128, 16, 8, 8, true><<<grid, 256>>>(z, W1, b1, h1, NROWS, HDIM, DDIM);
        gemm_bias_act<128, 128, 16, 8, 8, true><<<grid, 256>>>(h1, W2, b2, h2, NROWS, HDIM, HDIM);
        gemm_bias_act<128, 128, 16, 8, 8, true><<<grid, 256>>>(h2, W3, b3, h1, NROWS, HDIM, HDIM);
        gemm_bias_act<128, 128, 16, 8, 8, true><<<grid, 256>>>(h1, W4, b4, h2, NROWS, HDIM, HDIM);
        dim3 grid5(DDIM / 64, NROWS / 128);
        gemm_bias_act<128, 64, 16, 8, 8, false><<<grid5, 128>>>(h2, W5, b5, x, NROWS, DDIM, HDIM);
    }

    // pass 1
    {
        const size_t smemB = (size_t)2 * 64 * 129 * sizeof(float);
        cudaFuncSetAttribute(inner_pass<true>, cudaFuncAttributeMaxDynamicSharedMemorySize, (int)smemB);
        cudaFuncSetAttribute(inner_pass<false>, cudaFuncAttributeMaxDynamicSharedMemorySize, (int)smemB);
        dim3 grid(NFREQ / 128, NROWS / 128);
        inner_pass<true><<<grid, 256, smemB>>>(x, Fr, sCx, sSx);
        inner_pass<false><<<grid, 256, smemB>>>(data, Fr, sCy, sSy);
    }

    err_kernel<<<(NFREQ + 255) / 256, 256>>>();

    // pass 2
    {
        const size_t smemC = (size_t)(64 * 129 + 128 * 68) * sizeof(float);
        cudaFuncSetAttribute(pass2_kernel, cudaFuncAttributeMaxDynamicSharedMemorySize, (int)smemC);
        pass2_kernel<<<NROWS / 64, 256, smemC>>>(Fr);
    }

    rowsq_kernel<<<NROWS / 8, 256>>>();
    final_kernel<<<(NROWS + 255) / 256, 256>>>(out);
}

// round 3
// speedup vs baseline: 1.0051x; 1.0051x over previous
#include <cuda_runtime.h>
#include <math.h>

#define NROWS 16384
#define DDIM 64
#define HDIM 1024
#define NFREQ 4096

// ---------------- scratch (static device allocations; allowed) ----------------
__device__ float g_h1[(size_t)NROWS * HDIM];
__device__ float g_h2[(size_t)NROWS * HDIM];
__device__ float g_x[(size_t)NROWS * DDIM];
__device__ float g_inner[(size_t)NROWS * NFREQ];   // 256 MB
__device__ float g_V[(size_t)NROWS * DDIM];
__device__ float g_sCx[NFREQ];
__device__ float g_sSx[NFREQ];
__device__ float g_sCy[NFREQ];
__device__ float g_sSy[NFREQ];
__device__ float g_errC[NFREQ];
__device__ float g_errS[NFREQ];
__device__ float g_rowsq[NROWS];
__device__ float g_vtot;

__device__ __forceinline__ float selu_f(float v) {
    const float alpha = 1.6732632423543772f;
    const float scale = 1.0507009873554805f;
    return v > 0.0f ? scale * v : scale * alpha * expm1f(v);
}

__global__ void zero_kernel() {
    int i = blockIdx.x * blockDim.x + threadIdx.x;
    if (i < NFREQ) {
        g_sCx[i] = 0.f; g_sSx[i] = 0.f; g_sCy[i] = 0.f; g_sSy[i] = 0.f;
    }
    if (i == 0) g_vtot = 0.f;
}

// ---------------- fp32 tiled GEMM + bias (+SELU) ----------------
// C[M,N] = act(A[M,K] @ W[K,N] + b[N])
template<int BM, int BN, int BK, int TM, int TN, bool ACT>
__global__ void __launch_bounds__((BM / TM) * (BN / TN))
gemm_bias_act(const float* __restrict__ A, const float* __restrict__ W,
              const float* __restrict__ bias, float* __restrict__ C,
              int M, int N, int K)
{
    constexpr int THREADS = (BM / TM) * (BN / TN);
    __shared__ float As[BK][BM + 4];
    __shared__ float Ws[BK][BN];
    const int tx = threadIdx.x;
    const int tcol = tx % (BN / TN);
    const int trow = tx / (BN / TN);
    const int rowBase = blockIdx.y * BM;
    const int colBase = blockIdx.x * BN;

    float acc[TM][TN];
#pragma unroll
    for (int i = 0; i < TM; i++)
#pragma unroll
        for (int j = 0; j < TN; j++) acc[i][j] = 0.f;

    for (int k0 = 0; k0 < K; k0 += BK) {
        // A tile (BM x BK) -> As[k][m]  (float4 global loads)
        for (int i = tx; i < BM * (BK / 4); i += THREADS) {
            int m = i / (BK / 4);
            int kq = (i % (BK / 4)) * 4;
            const float4 v = *reinterpret_cast<const float4*>(
                &A[(size_t)(rowBase + m) * K + k0 + kq]);
            As[kq + 0][m] = v.x; As[kq + 1][m] = v.y;
            As[kq + 2][m] = v.z; As[kq + 3][m] = v.w;
        }
        // W tile (BK x BN)
        for (int i = tx; i < BK * (BN / 4); i += THREADS) {
            int kk = i / (BN / 4);
            int nq = (i % (BN / 4)) * 4;
            *reinterpret_cast<float4*>(&Ws[kk][nq]) =
                *reinterpret_cast<const float4*>(
                    &W[(size_t)(k0 + kk) * N + colBase + nq]);
        }
        __syncthreads();
#pragma unroll
        for (int kk = 0; kk < BK; kk++) {
            float a[TM], w[TN];
#pragma unroll
            for (int i = 0; i < TM; i++) a[i] = As[kk][trow * TM + i];
#pragma unroll
            for (int j = 0; j < TN; j++) w[j] = Ws[kk][tcol * TN + j];
#pragma unroll
            for (int i = 0; i < TM; i++)
#pragma unroll
                for (int j = 0; j < TN; j++)
                    acc[i][j] = fmaf(a[i], w[j], acc[i][j]);
        }
        __syncthreads();
    }
#pragma unroll
    for (int i = 0; i < TM; i++) {
        const int m = rowBase + trow * TM + i;
#pragma unroll
        for (int j = 0; j < TN; j++) {
            const int n = colBase + tcol * TN + j;
            float v = acc[i][j] + bias[n];
            if (ACT) v = selu_f(v);
            C[(size_t)m * N + n] = v;
        }
    }
}

// ---------------- pass 1: inner = X @ (2*Fr)^T, column means of cos/sin ------
// Block: 128 rows x 128 freqs, 256 threads, 8x8 per thread. K = 64 (full).
template<bool STORE>
__global__ void __launch_bounds__(256)
inner_pass(const float* __restrict__ X, const float* __restrict__ Fr,
           float* __restrict__ sumC, float* __restrict__ sumS)
{
    extern __shared__ float sm[];
    float* Xs = sm;               // [64][129] : Xs[k*129 + r]
    float* Fs = sm + 64 * 129;    // [64][129] : Fs[k*129 + f]
    __shared__ float redC[128];
    __shared__ float redS[128];

    const int tx = threadIdx.x;
    const int rowBase = blockIdx.y * 128;
    const int fBase = blockIdx.x * 128;

    for (int q = tx; q < 128 * 16; q += 256) {
        int r = q >> 4;
        int d4 = (q & 15) << 2;
        float4 v = *reinterpret_cast<const float4*>(
            &X[(size_t)(rowBase + r) * DDIM + d4]);
        Xs[(d4 + 0) * 129 + r] = v.x;
        Xs[(d4 + 1) * 129 + r] = v.y;
        Xs[(d4 + 2) * 129 + r] = v.z;
        Xs[(d4 + 3) * 129 + r] = v.w;
    }
    for (int q = tx; q < 128 * 16; q += 256) {
        int f = q >> 4;
        int d4 = (q & 15) << 2;
        float4 v = *reinterpret_cast<const float4*>(
            &Fr[(size_t)(fBase + f) * DDIM + d4]);
        Fs[(d4 + 0) * 129 + f] = 2.0f * v.x;
        Fs[(d4 + 1) * 129 + f] = 2.0f * v.y;
        Fs[(d4 + 2) * 129 + f] = 2.0f * v.z;
        Fs[(d4 + 3) * 129 + f] = 2.0f * v.w;
    }
    __syncthreads();

    const int trow = tx >> 4;   // 0..15 (row group of 8)
    const int tcol = tx & 15;   // 0..15 (freq group of 8)

    float acc[8][8];
#pragma unroll
    for (int i = 0; i < 8; i++)
#pragma unroll
        for (int j = 0; j < 8; j++) acc[i][j] = 0.f;

#pragma unroll 8
    for (int k = 0; k < 64; k++) {
        float a[8], w[8];
#pragma unroll
        for (int i = 0; i < 8; i++) a[i] = Xs[k * 129 + trow * 8 + i];
#pragma unroll
        for (int j = 0; j < 8; j++) w[j] = Fs[k * 129 + tcol * 8 + j];
#pragma unroll
        for (int i = 0; i < 8; i++)
#pragma unroll
            for (int j = 0; j < 8; j++)
                acc[i][j] = fmaf(a[i], w[j], acc[i][j]);
    }

    float cpart[8], spart[8];
#pragma unroll
    for (int j = 0; j < 8; j++) { cpart[j] = 0.f; spart[j] = 0.f; }

#pragma unroll
    for (int i = 0; i < 8; i++) {
        if (STORE) {
            size_t base = (size_t)(rowBase + trow * 8 + i) * NFREQ + fBase + tcol * 8;
            float4 v0 = make_float4(acc[i][0], acc[i][1], acc[i][2], acc[i][3]);
            float4 v1 = make_float4(acc[i][4], acc[i][5], acc[i][6], acc[i][7]);
            *reinterpret_cast<float4*>(&g_inner[base]) = v0;
            *reinterpret_cast<float4*>(&g_inner[base + 4]) = v1;
        }
#pragma unroll
        for (int j = 0; j < 8; j++) {
            float s, c;
            sincosf(acc[i][j], &s, &c);
            cpart[j] += c;
            spart[j] += s;
        }
    }

    if (tx < 128) { redC[tx] = 0.f; redS[tx] = 0.f; }
    __syncthreads();
#pragma unroll
    for (int j = 0; j < 8; j++) {
        atomicAdd(&redC[tcol * 8 + j], cpart[j]);
        atomicAdd(&redS[tcol * 8 + j], spart[j]);
    }
    __syncthreads();
    if (tx < 128) {
        atomicAdd(&sumC[fBase + tx], redC[tx]);
        atomicAdd(&sumS[fBase + tx], redS[tx]);
    }
}

__global__ void err_kernel() {
    int f = blockIdx.x * blockDim.x + threadIdx.x;
    if (f < NFREQ) {
        const float inv = 1.0f / (float)NROWS;   // N == M == 16384
        g_errC[f] = (g_sCx[f] - g_sCy[f]) * inv;
        g_errS[f] = (g_sSx[f] - g_sSy[f]) * inv;
    }
}

// ---------------- pass 2: V = (-2/(N*NF)) * coeff @ F ------------------------
// Block: 64 rows, loop over freq in chunks of 128. 256 threads.
// coeff computed in smem from stored inner; then smem GEMM 64x64x128 per chunk.
__global__ void __launch_bounds__(256)
pass2_kernel(const float* __restrict__ Fr)
{
    extern __shared__ float sm[];
    float* coeffS = sm;                 // [64][129]
    float* Fs = sm + 64 * 129;          // [128][68]
    __shared__ float eC[128];
    __shared__ float eS[128];

    const int tx = threadIdx.x;
    const int rowBase = blockIdx.x * 64;
    const int trow = tx >> 4;   // 0..15 -> rows trow*4..+3
    const int tcol = tx & 15;   // 0..15 -> dims tcol*4..+3

    float acc[4][4];
#pragma unroll
    for (int i = 0; i < 4; i++)
#pragma unroll
        for (int j = 0; j < 4; j++) acc[i][j] = 0.f;

    for (int fc = 0; fc < NFREQ; fc += 128) {
        for (int q = tx; q < 128 * 16; q += 256) {
            int f = q >> 4;
            int d4 = (q & 15) << 2;
            float4 v = *reinterpret_cast<const float4*>(
                &Fr[(size_t)(fc + f) * DDIM + d4]);
            Fs[f * 68 + d4 + 0] = 2.0f * v.x;
            Fs[f * 68 + d4 + 1] = 2.0f * v.y;
            Fs[f * 68 + d4 + 2] = 2.0f * v.z;
            Fs[f * 68 + d4 + 3] = 2.0f * v.w;
        }
        if (tx < 128) { eC[tx] = g_errC[fc + tx]; eS[tx] = g_errS[fc + tx]; }
        __syncthreads();

        // coeff tile 64x128
        for (int e = tx; e < 64 * 128; e += 256) {
            int r = e >> 7;
            int fl = e & 127;
            float v = g_inner[(size_t)(rowBase + r) * NFREQ + fc + fl];
            float s, c;
            sincosf(v, &s, &c);
            coeffS[r * 129 + fl] = -eC[fl] * s + eS[fl] * c;
        }
        __syncthreads();

#pragma unroll 4
        for (int f = 0; f < 128; f++) {
            float a[4];
#pragma unroll
            for (int i = 0; i < 4; i++) a[i] = coeffS[(trow * 4 + i) * 129 + f];
            float4 wv = *reinterpret_cast<const float4*>(&Fs[f * 68 + tcol * 4]);
            float w[4] = { wv.x, wv.y, wv.z, wv.w };
#pragma unroll
            for (int i = 0; i < 4; i++)
#pragma unroll
                for (int j = 0; j < 4; j++)
                    acc[i][j] = fmaf(a[i], w[j], acc[i][j]);
        }
        __syncthreads();
    }

    const float fac = -2.0f / ((float)NROWS * (float)NFREQ);
#pragma unroll
    for (int i = 0; i < 4; i++) {
        const int m = rowBase + trow * 4 + i;
        float4 v = make_float4(acc[i][0] * fac, acc[i][1] * fac,
                               acc[i][2] * fac, acc[i][3] * fac);
        *reinterpret_cast<float4*>(&g_V[(size_t)m * DDIM + tcol * 4]) = v;
    }
}

// ---------------- row sum of squares + global total --------------------------
__global__ void __launch_bounds__(256)
rowsq_kernel()
{
    const int row = blockIdx.x * 8 + (threadIdx.x >> 5);
    const int lane = threadIdx.x & 31;
    float v0 = g_V[(size_t)row * DDIM + lane];
    float v1 = g_V[(size_t)row * DDIM + lane + 32];
    float s = v0 * v0 + v1 * v1;
#pragma unroll
    for (int o = 16; o > 0; o >>= 1) s += __shfl_down_sync(0xFFFFFFFFu, s, o);
    if (lane == 0) {
        g_rowsq[row] = s;
        atomicAdd(&g_vtot, s);
    }
}

__global__ void final_kernel(float* __restrict__ out)
{
    int i = blockIdx.x * blockDim.x + threadIdx.x;
    if (i < NROWS) {
        float mean = g_vtot * (1.0f / ((float)NROWS * (float)DDIM));
        out[i] = g_rowsq[i] / (mean + 1e-8f);
    }
}

// ---------------- launch -----------------------------------------------------
extern "C" void kernel_launch(void* const* d_in, const int* in_sizes, int n_in,
                              void* d_out, int out_size)
{
    const float* data = (const float*)d_in[0];
    const float* z    = (const float*)d_in[1];
    const float* Fr   = (const float*)d_in[2];
    const float* W1   = (const float*)d_in[3];
    const float* b1   = (const float*)d_in[4];
    const float* W2   = (const float*)d_in[5];
    const float* b2   = (const float*)d_in[6];
    const float* W3   = (const float*)d_in[7];
    const float* b3   = (const float*)d_in[8];
    const float* W4   = (const float*)d_in[9];
    const float* b4   = (const float*)d_in[10];
    const float* W5   = (const float*)d_in[11];
    const float* b5   = (const float*)d_in[12];
    float* out = (float*)d_out;

    float *h1, *h2, *x, *sCx, *sSx, *sCy, *sSy;
    cudaGetSymbolAddress((void**)&h1, g_h1);
    cudaGetSymbolAddress((void**)&h2, g_h2);
    cudaGetSymbolAddress((void**)&x, g_x);
    cudaGetSymbolAddress((void**)&sCx, g_sCx);
    cudaGetSymbolAddress((void**)&sSx, g_sSx);
    cudaGetSymbolAddress((void**)&sCy, g_sCy);
    cudaGetSymbolAddress((void**)&sSy, g_sSy);

    zero_kernel<<<(NFREQ + 255) / 256, 256>>>();

    // MLP
    {
        dim3 grid(HDIM / 128, NROWS / 128);
        gemm_bias_act<128, 128, 16, 8, 8, true><<<grid, 256>>>(z, W1, b1, h1, NROWS, HDIM, DDIM);
        gemm_bias_act<128, 128, 16, 8, 8, true><<<grid, 256>>>(h1, W2, b2, h2, NROWS, HDIM, HDIM);
        gemm_bias_act<128, 128, 16, 8, 8, true><<<grid, 256>>>(h2, W3, b3, h1, NROWS, HDIM, HDIM);
        gemm_bias_act<128, 128, 16, 8, 8, true><<<grid, 256>>>(h1, W4, b4, h2, NROWS, HDIM, HDIM);
        dim3 grid5(DDIM / 64, NROWS / 128);
        gemm_bias_act<128, 64, 16, 8, 8, false><<<grid5, 128>>>(h2, W5, b5, x, NROWS, DDIM, HDIM);
    }

    // pass 1
    {
        const size_t smemB = (size_t)2 * 64 * 129 * sizeof(float);
        cudaFuncSetAttribute(inner_pass<true>, cudaFuncAttributeMaxDynamicSharedMemorySize, (int)smemB);
        cudaFuncSetAttribute(inner_pass<false>, cudaFuncAttributeMaxDynamicSharedMemorySize, (int)smemB);
        dim3 grid(NFREQ / 128, NROWS / 128);
        inner_pass<true><<<grid, 256, smemB>>>(x, Fr, sCx, sSx);
        inner_pass<false><<<grid, 256, smemB>>>(data, Fr, sCy, sSy);
    }

    err_kernel<<<(NFREQ + 255) / 256, 256>>>();

    // pass 2
    {
        const size_t smemC = (size_t)(64 * 129 + 128 * 68) * sizeof(float);
        cudaFuncSetAttribute(pass2_kernel, cudaFuncAttributeMaxDynamicSharedMemorySize, (int)smemC);
        pass2_kernel<<<NROWS / 64, 256, smemC>>>(Fr);
    }

    rowsq_kernel<<<NROWS / 8, 256>>>();
    final_kernel<<<(NROWS + 255) / 256, 256>>>(out);
}